// round 1
// baseline (speedup 1.0000x reference)
#include <cuda_runtime.h>

#define NMAX_NODES 50000
#define NMAX_EDGES 800000

// Scratch (device globals; no allocation allowed)
__device__ float g_z[NMAX_NODES * 128];
__device__ float g_ssrc[NMAX_NODES];
__device__ float g_sdst[NMAX_NODES];
__device__ float g_denom[NMAX_NODES];
__device__ float g_w[NMAX_EDGES];

__device__ __forceinline__ float warp_sum(float v) {
#pragma unroll
    for (int o = 16; o; o >>= 1) v += __shfl_xor_sync(0xffffffffu, v, o);
    return v;
}

__device__ __forceinline__ void red_add_v4(float* p, float x, float y, float z, float w) {
    asm volatile("red.global.add.v4.f32 [%0], {%1, %2, %3, %4};"
                 :: "l"(p), "f"(x), "f"(y), "f"(z), "f"(w) : "memory");
}

// ---------------------------------------------------------------------------
// K0: zero output h and denom
// ---------------------------------------------------------------------------
__global__ void k_zero(float* __restrict__ out, int n_out4, int n_den4) {
    int i = blockIdx.x * blockDim.x + threadIdx.x;
    float4 z4 = make_float4(0.f, 0.f, 0.f, 0.f);
    if (i < n_out4) {
        ((float4*)out)[i] = z4;
    } else if (i < n_out4 + n_den4) {
        ((float4*)g_denom)[i - n_out4] = z4;
    }
}

// ---------------------------------------------------------------------------
// K1: z = nfeats @ W_fc^T   (50000x128 @ 128x128)
// Block: 128 threads, tile 64 rows x 128 cols, 8x8 micro-tile per thread.
// smem: sW[k][o] (64KB, W transposed) + nT[k][r] (stride 72, 36KB)
// ---------------------------------------------------------------------------
#define NT_STRIDE 72
#define GEMM_SMEM (65536 + 128 * NT_STRIDE * 4)

__global__ __launch_bounds__(128) void k_gemm(const float* __restrict__ nf,
                                              const float* __restrict__ W,
                                              int n_nodes) {
    extern __shared__ float sm[];
    float* sW = sm;              // [128][128]  sW[k*128+o] = W[o][k]
    float* nT = sm + 16384;      // [128][NT_STRIDE]  nT[k*72+r] = nf[rowBase+r][k]
    int tid = threadIdx.x;
    int rowBase = blockIdx.x * 64;

    // Load W transposed: thread tid handles W row o=tid
    {
        int o = tid;
#pragma unroll
        for (int j = 0; j < 32; j++) {
            float4 v = ((const float4*)W)[o * 32 + j];
            int k = j * 4;
            sW[(k + 0) * 128 + o] = v.x;
            sW[(k + 1) * 128 + o] = v.y;
            sW[(k + 2) * 128 + o] = v.z;
            sW[(k + 3) * 128 + o] = v.w;
        }
    }
    // Load node-feature tile transposed: 2 threads per row (k halves)
    {
        int rl = tid & 63;
        int kh = tid >> 6;
        int r = rowBase + rl;
        bool ok = (r < n_nodes);
#pragma unroll
        for (int j = 0; j < 16; j++) {
            int k0 = kh * 64 + j * 4;
            float4 v = ok ? ((const float4*)nf)[r * 32 + (k0 >> 2)]
                          : make_float4(0.f, 0.f, 0.f, 0.f);
            nT[(k0 + 0) * NT_STRIDE + rl] = v.x;
            nT[(k0 + 1) * NT_STRIDE + rl] = v.y;
            nT[(k0 + 2) * NT_STRIDE + rl] = v.z;
            nT[(k0 + 3) * NT_STRIDE + rl] = v.w;
        }
    }
    __syncthreads();

    int tx = tid & 15;   // 16 col-groups x 8 cols
    int ty = tid >> 4;   // 8 row-groups  x 8 rows
    float c[8][8];
#pragma unroll
    for (int i = 0; i < 8; i++)
#pragma unroll
        for (int j = 0; j < 8; j++) c[i][j] = 0.f;

#pragma unroll 4
    for (int k = 0; k < 128; k++) {
        float4 a0 = *(float4*)&nT[k * NT_STRIDE + ty * 8];
        float4 a1 = *(float4*)&nT[k * NT_STRIDE + ty * 8 + 4];
        float4 b0 = *(float4*)&sW[k * 128 + tx * 8];
        float4 b1 = *(float4*)&sW[k * 128 + tx * 8 + 4];
        float a[8] = {a0.x, a0.y, a0.z, a0.w, a1.x, a1.y, a1.z, a1.w};
        float b[8] = {b0.x, b0.y, b0.z, b0.w, b1.x, b1.y, b1.z, b1.w};
#pragma unroll
        for (int i = 0; i < 8; i++)
#pragma unroll
            for (int j = 0; j < 8; j++) c[i][j] += a[i] * b[j];
    }

#pragma unroll
    for (int i = 0; i < 8; i++) {
        int r = rowBase + ty * 8 + i;
        if (r < n_nodes) {
            ((float4*)g_z)[r * 32 + tx * 2] =
                make_float4(c[i][0], c[i][1], c[i][2], c[i][3]);
            ((float4*)g_z)[r * 32 + tx * 2 + 1] =
                make_float4(c[i][4], c[i][5], c[i][6], c[i][7]);
        }
    }
}

// ---------------------------------------------------------------------------
// K2: s_src[n] = z[n]·a_src ; s_dst[n] = z[n]·a_dst   (warp per node)
// ---------------------------------------------------------------------------
__global__ void k_sdot(const float* __restrict__ Wa, int n_nodes) {
    int node = (blockIdx.x * blockDim.x + threadIdx.x) >> 5;
    int lane = threadIdx.x & 31;
    if (node >= n_nodes) return;
    float4 z4 = ((const float4*)g_z)[node * 32 + lane];
    float4 as = ((const float4*)Wa)[lane];               // a_src = Wa[0:128]
    float4 ad = ((const float4*)(Wa + 160))[lane];       // a_dst = Wa[160:288]
    float v1 = z4.x * as.x + z4.y * as.y + z4.z * as.z + z4.w * as.w;
    float v2 = z4.x * ad.x + z4.y * ad.y + z4.z * ad.z + z4.w * ad.w;
    v1 = warp_sum(v1);
    v2 = warp_sum(v2);
    if (lane == 0) {
        g_ssrc[node] = v1;
        g_sdst[node] = v2;
    }
}

// ---------------------------------------------------------------------------
// K3: per-edge  w = exp(leaky_relu(s_src[src]+e·a_e+s_dst[dst]))
//     denom[dst] += w     (warp per edge; max-shift cancels in alpha)
// ---------------------------------------------------------------------------
__global__ void k_edge_w(const float* __restrict__ ef, const float* __restrict__ Wa,
                         const int* __restrict__ src, const int* __restrict__ dst,
                         int n_edges) {
    int e = (blockIdx.x * blockDim.x + threadIdx.x) >> 5;
    int lane = threadIdx.x & 31;
    if (e >= n_edges) return;
    float v = ef[e * 32 + lane] * Wa[128 + lane];  // a_e = Wa[128:160]
    v = warp_sum(v);
    if (lane == 0) {
        float ev = g_ssrc[src[e]] + v + g_sdst[dst[e]];
        ev = (ev > 0.f) ? ev : 0.01f * ev;
        float w = __expf(ev);
        g_w[e] = w;
        atomicAdd(&g_denom[dst[e]], w);
    }
}

// ---------------------------------------------------------------------------
// K4: h[dst] += (w/denom[dst]) * z[src]   (warp per edge, red.add.v4)
// ---------------------------------------------------------------------------
__global__ void k_scatter(const int* __restrict__ src, const int* __restrict__ dst,
                          float* __restrict__ out, int n_edges) {
    int e = (blockIdx.x * blockDim.x + threadIdx.x) >> 5;
    int lane = threadIdx.x & 31;
    if (e >= n_edges) return;
    int s = src[e];
    int d = dst[e];
    float alpha = g_w[e] / g_denom[d];
    float4 z4 = ((const float4*)g_z)[s * 32 + lane];
    red_add_v4(out + d * 128 + lane * 4,
               alpha * z4.x, alpha * z4.y, alpha * z4.z, alpha * z4.w);
}

// ---------------------------------------------------------------------------
extern "C" void kernel_launch(void* const* d_in, const int* in_sizes, int n_in,
                              void* d_out, int out_size) {
    const float* nf  = (const float*)d_in[0];
    const float* ef  = (const float*)d_in[1];
    const float* Wfc = (const float*)d_in[2];
    const float* Wa  = (const float*)d_in[3];
    const int*   src = (const int*)d_in[4];
    const int*   dst = (const int*)d_in[5];
    float* out = (float*)d_out;

    int n_nodes = in_sizes[0] / 128;
    int n_edges = in_sizes[4];

    cudaFuncSetAttribute(k_gemm, cudaFuncAttributeMaxDynamicSharedMemorySize, GEMM_SMEM);

    int n_out4 = out_size / 4;
    int n_den4 = (n_nodes + 3) / 4;
    int nz = n_out4 + n_den4;
    k_zero<<<(nz + 255) / 256, 256>>>(out, n_out4, n_den4);
    k_gemm<<<(n_nodes + 63) / 64, 128, GEMM_SMEM>>>(nf, Wfc, n_nodes);
    k_sdot<<<(n_nodes + 7) / 8, 256>>>(Wa, n_nodes);
    k_edge_w<<<(n_edges + 7) / 8, 256>>>(ef, Wa, src, dst, n_edges);
    k_scatter<<<(n_edges + 7) / 8, 256>>>(src, dst, out, n_edges);
}

// round 2
// speedup vs baseline: 1.7526x; 1.7526x over previous
#include <cuda_runtime.h>

#define NMAX_NODES 50000
#define NMAX_EDGES 800000

// Scratch (device globals; no allocation allowed)
__device__ float g_z[NMAX_NODES * 128];
__device__ float g_ssrc[NMAX_NODES];
__device__ float g_sdst[NMAX_NODES];
__device__ float g_denom[NMAX_NODES];
__device__ float g_w[NMAX_EDGES];
__device__ int   g_deg[NMAX_NODES];
__device__ int   g_start[NMAX_NODES];
__device__ int   g_cursor[NMAX_NODES];
__device__ int   g_blocksum[256];
__device__ int   g_perm[NMAX_EDGES];

__device__ __forceinline__ float warp_sum(float v) {
#pragma unroll
    for (int o = 16; o; o >>= 1) v += __shfl_xor_sync(0xffffffffu, v, o);
    return v;
}

// ---------------------------------------------------------------------------
// K0: zero denom (float) and deg (int)
// ---------------------------------------------------------------------------
__global__ void k_zero(int n_nodes) {
    int i = blockIdx.x * blockDim.x + threadIdx.x;
    if (i < n_nodes) {
        g_denom[i] = 0.f;
        g_deg[i] = 0;
    }
}

// ---------------------------------------------------------------------------
// K1: z = nfeats @ W_fc^T   (50000x128 @ 128x128)
// Block: 128 threads, tile 64 rows x 128 cols, 8x8 micro-tile per thread.
// ---------------------------------------------------------------------------
#define NT_STRIDE 72
#define GEMM_SMEM (65536 + 128 * NT_STRIDE * 4)

__global__ __launch_bounds__(128) void k_gemm(const float* __restrict__ nf,
                                              const float* __restrict__ W,
                                              int n_nodes) {
    extern __shared__ float sm[];
    float* sW = sm;              // [128][128]  sW[k*128+o] = W[o][k]
    float* nT = sm + 16384;      // [128][NT_STRIDE]  nT[k*72+r] = nf[rowBase+r][k]
    int tid = threadIdx.x;
    int rowBase = blockIdx.x * 64;

    {
        int o = tid;
#pragma unroll
        for (int j = 0; j < 32; j++) {
            float4 v = ((const float4*)W)[o * 32 + j];
            int k = j * 4;
            sW[(k + 0) * 128 + o] = v.x;
            sW[(k + 1) * 128 + o] = v.y;
            sW[(k + 2) * 128 + o] = v.z;
            sW[(k + 3) * 128 + o] = v.w;
        }
    }
    {
        int rl = tid & 63;
        int kh = tid >> 6;
        int r = rowBase + rl;
        bool ok = (r < n_nodes);
#pragma unroll
        for (int j = 0; j < 16; j++) {
            int k0 = kh * 64 + j * 4;
            float4 v = ok ? ((const float4*)nf)[r * 32 + (k0 >> 2)]
                          : make_float4(0.f, 0.f, 0.f, 0.f);
            nT[(k0 + 0) * NT_STRIDE + rl] = v.x;
            nT[(k0 + 1) * NT_STRIDE + rl] = v.y;
            nT[(k0 + 2) * NT_STRIDE + rl] = v.z;
            nT[(k0 + 3) * NT_STRIDE + rl] = v.w;
        }
    }
    __syncthreads();

    int tx = tid & 15;
    int ty = tid >> 4;
    float c[8][8];
#pragma unroll
    for (int i = 0; i < 8; i++)
#pragma unroll
        for (int j = 0; j < 8; j++) c[i][j] = 0.f;

#pragma unroll 4
    for (int k = 0; k < 128; k++) {
        float4 a0 = *(float4*)&nT[k * NT_STRIDE + ty * 8];
        float4 a1 = *(float4*)&nT[k * NT_STRIDE + ty * 8 + 4];
        float4 b0 = *(float4*)&sW[k * 128 + tx * 8];
        float4 b1 = *(float4*)&sW[k * 128 + tx * 8 + 4];
        float a[8] = {a0.x, a0.y, a0.z, a0.w, a1.x, a1.y, a1.z, a1.w};
        float b[8] = {b0.x, b0.y, b0.z, b0.w, b1.x, b1.y, b1.z, b1.w};
#pragma unroll
        for (int i = 0; i < 8; i++)
#pragma unroll
            for (int j = 0; j < 8; j++) c[i][j] += a[i] * b[j];
    }

#pragma unroll
    for (int i = 0; i < 8; i++) {
        int r = rowBase + ty * 8 + i;
        if (r < n_nodes) {
            ((float4*)g_z)[r * 32 + tx * 2] =
                make_float4(c[i][0], c[i][1], c[i][2], c[i][3]);
            ((float4*)g_z)[r * 32 + tx * 2 + 1] =
                make_float4(c[i][4], c[i][5], c[i][6], c[i][7]);
        }
    }
}

// ---------------------------------------------------------------------------
// K2: s_src[n] = z[n]·a_src ; s_dst[n] = z[n]·a_dst   (warp per node)
// ---------------------------------------------------------------------------
__global__ void k_sdot(const float* __restrict__ Wa, int n_nodes) {
    int node = (blockIdx.x * blockDim.x + threadIdx.x) >> 5;
    int lane = threadIdx.x & 31;
    if (node >= n_nodes) return;
    float4 z4 = ((const float4*)g_z)[node * 32 + lane];
    float4 as = ((const float4*)Wa)[lane];               // a_src = Wa[0:128]
    float4 ad = ((const float4*)(Wa + 160))[lane];       // a_dst = Wa[160:288]
    float v1 = z4.x * as.x + z4.y * as.y + z4.z * as.z + z4.w * as.w;
    float v2 = z4.x * ad.x + z4.y * ad.y + z4.z * ad.z + z4.w * ad.w;
    v1 = warp_sum(v1);
    v2 = warp_sum(v2);
    if (lane == 0) {
        g_ssrc[node] = v1;
        g_sdst[node] = v2;
    }
}

// ---------------------------------------------------------------------------
// K3: thread per edge:  w = exp(leaky_relu(s_src[src]+e·a_e+s_dst[dst]))
//     denom[dst] += w ; deg[dst]++  (histogram fused)
// ---------------------------------------------------------------------------
__global__ __launch_bounds__(256) void k_edge_w(const float* __restrict__ ef,
                                                const float* __restrict__ Wa,
                                                const int* __restrict__ src,
                                                const int* __restrict__ dst,
                                                int n_edges) {
    __shared__ float sa[32];
    if (threadIdx.x < 32) sa[threadIdx.x] = Wa[128 + threadIdx.x];  // a_e
    __syncthreads();
    int e = blockIdx.x * blockDim.x + threadIdx.x;
    if (e >= n_edges) return;
    const float4* p = (const float4*)(ef + (size_t)e * 32);
    float v = 0.f;
#pragma unroll
    for (int j = 0; j < 8; j++) {
        float4 x = __ldg(&p[j]);
        v += x.x * sa[4 * j] + x.y * sa[4 * j + 1] +
             x.z * sa[4 * j + 2] + x.w * sa[4 * j + 3];
    }
    int s = src[e];
    int d = dst[e];
    float ev = __ldg(&g_ssrc[s]) + v + __ldg(&g_sdst[d]);
    ev = (ev > 0.f) ? ev : 0.01f * ev;
    float w = __expf(ev);
    g_w[e] = w;
    atomicAdd(&g_denom[d], w);
    atomicAdd(&g_deg[d], 1);
}

// ---------------------------------------------------------------------------
// K4a/b/c: exclusive prefix scan of deg -> start (and cursor copy)
// 50000 elems -> 196 blocks of 256; blocksums scanned by one block of 256.
// ---------------------------------------------------------------------------
__global__ void k_scan1(int n) {
    __shared__ int s[256];
    int i = blockIdx.x * 256 + threadIdx.x;
    int v = (i < n) ? g_deg[i] : 0;
    s[threadIdx.x] = v;
    __syncthreads();
#pragma unroll
    for (int off = 1; off < 256; off <<= 1) {
        int t = (threadIdx.x >= off) ? s[threadIdx.x - off] : 0;
        __syncthreads();
        s[threadIdx.x] += t;
        __syncthreads();
    }
    if (i < n) g_start[i] = s[threadIdx.x] - v;  // exclusive
    if (threadIdx.x == 255) g_blocksum[blockIdx.x] = s[255];
}

__global__ void k_scan2(int nb) {
    __shared__ int s[256];
    int v = (threadIdx.x < nb) ? g_blocksum[threadIdx.x] : 0;
    s[threadIdx.x] = v;
    __syncthreads();
#pragma unroll
    for (int off = 1; off < 256; off <<= 1) {
        int t = (threadIdx.x >= off) ? s[threadIdx.x - off] : 0;
        __syncthreads();
        s[threadIdx.x] += t;
        __syncthreads();
    }
    if (threadIdx.x < nb) g_blocksum[threadIdx.x] = s[threadIdx.x] - v;  // exclusive
}

__global__ void k_scan3(int n) {
    int i = blockIdx.x * 256 + threadIdx.x;
    if (i < n) {
        int st = g_start[i] + g_blocksum[blockIdx.x];
        g_start[i] = st;
        g_cursor[i] = st;
    }
}

// ---------------------------------------------------------------------------
// K5: place edge ids into dst-sorted order
// ---------------------------------------------------------------------------
__global__ void k_place(const int* __restrict__ dst, int n_edges) {
    int e = blockIdx.x * blockDim.x + threadIdx.x;
    if (e >= n_edges) return;
    int d = dst[e];
    int pos = atomicAdd(&g_cursor[d], 1);
    g_perm[pos] = e;
}

// ---------------------------------------------------------------------------
// K6: warp per dst node: h[d] = sum_e alpha_e * z[src_e]  (no atomics)
// ---------------------------------------------------------------------------
__global__ __launch_bounds__(256) void k_agg(const int* __restrict__ src,
                                             float* __restrict__ out,
                                             int n_nodes) {
    int d = (blockIdx.x * blockDim.x + threadIdx.x) >> 5;
    int lane = threadIdx.x & 31;
    if (d >= n_nodes) return;
    int start = g_start[d];
    int deg = g_deg[d];
    float dinv = (deg > 0) ? 1.0f / g_denom[d] : 0.f;
    float4 acc = make_float4(0.f, 0.f, 0.f, 0.f);

    for (int i = 0; i < deg; i += 32) {
        int s = 0;
        float wv = 0.f;
        if (i + lane < deg) {
            int e = g_perm[start + i + lane];
            s = __ldg(&src[e]);
            wv = g_w[e];
        }
        int cnt = min(32, deg - i);
        for (int j = 0; j < cnt; j++) {
            int sj = __shfl_sync(0xffffffffu, s, j);
            float aj = __shfl_sync(0xffffffffu, wv, j) * dinv;
            float4 z4 = ((const float4*)g_z)[sj * 32 + lane];
            acc.x += aj * z4.x;
            acc.y += aj * z4.y;
            acc.z += aj * z4.z;
            acc.w += aj * z4.w;
        }
    }
    ((float4*)out)[d * 32 + lane] = acc;
}

// ---------------------------------------------------------------------------
extern "C" void kernel_launch(void* const* d_in, const int* in_sizes, int n_in,
                              void* d_out, int out_size) {
    const float* nf  = (const float*)d_in[0];
    const float* ef  = (const float*)d_in[1];
    const float* Wfc = (const float*)d_in[2];
    const float* Wa  = (const float*)d_in[3];
    const int*   src = (const int*)d_in[4];
    const int*   dst = (const int*)d_in[5];
    float* out = (float*)d_out;

    int n_nodes = in_sizes[0] / 128;
    int n_edges = in_sizes[4];
    int nscan = (n_nodes + 255) / 256;  // 196 (must be <= 256)

    cudaFuncSetAttribute(k_gemm, cudaFuncAttributeMaxDynamicSharedMemorySize, GEMM_SMEM);

    k_zero<<<(n_nodes + 255) / 256, 256>>>(n_nodes);
    k_gemm<<<(n_nodes + 63) / 64, 128, GEMM_SMEM>>>(nf, Wfc, n_nodes);
    k_sdot<<<(n_nodes + 7) / 8, 256>>>(Wa, n_nodes);
    k_edge_w<<<(n_edges + 255) / 256, 256>>>(ef, Wa, src, dst, n_edges);
    k_scan1<<<nscan, 256>>>(n_nodes);
    k_scan2<<<1, 256>>>(nscan);
    k_scan3<<<nscan, 256>>>(n_nodes);
    k_place<<<(n_edges + 255) / 256, 256>>>(dst, n_edges);
    k_agg<<<(n_nodes + 7) / 8, 256>>>(src, out, n_nodes);
}

// round 3
// speedup vs baseline: 1.8355x; 1.0473x over previous
#include <cuda_runtime.h>
#include <cuda_fp16.h>

#define NMAX_NODES 50000
#define NMAX_EDGES 800000

// Scratch (device globals; no allocation allowed)
__device__ float  g_z[NMAX_NODES * 128];
__device__ __half g_zh[NMAX_NODES * 128];
__device__ float  g_ssrc[NMAX_NODES];
__device__ float  g_sdst[NMAX_NODES];
__device__ float  g_se[NMAX_EDGES];
__device__ int    g_deg[NMAX_NODES];
__device__ int    g_start[NMAX_NODES];
__device__ int    g_cursor[NMAX_NODES];
__device__ int    g_blocksum[256];
__device__ int    g_psrc[NMAX_EDGES];
__device__ float  g_pw[NMAX_EDGES];

__device__ __forceinline__ float warp_sum(float v) {
#pragma unroll
    for (int o = 16; o; o >>= 1) v += __shfl_xor_sync(0xffffffffu, v, o);
    return v;
}

// ---------------------------------------------------------------------------
// K0: zero deg
// ---------------------------------------------------------------------------
__global__ void k_zero(int n_nodes) {
    int i = blockIdx.x * blockDim.x + threadIdx.x;
    if (i < n_nodes) g_deg[i] = 0;
}

// ---------------------------------------------------------------------------
// K1: z = nfeats @ W_fc^T  (also writes fp16 copy for the agg gather)
// ---------------------------------------------------------------------------
#define NT_STRIDE 72
#define GEMM_SMEM (65536 + 128 * NT_STRIDE * 4)

__global__ __launch_bounds__(128) void k_gemm(const float* __restrict__ nf,
                                              const float* __restrict__ W,
                                              int n_nodes) {
    extern __shared__ float sm[];
    float* sW = sm;              // [128][128]  sW[k*128+o] = W[o][k]
    float* nT = sm + 16384;      // [128][NT_STRIDE]
    int tid = threadIdx.x;
    int rowBase = blockIdx.x * 64;

    {
        int o = tid;
#pragma unroll
        for (int j = 0; j < 32; j++) {
            float4 v = ((const float4*)W)[o * 32 + j];
            int k = j * 4;
            sW[(k + 0) * 128 + o] = v.x;
            sW[(k + 1) * 128 + o] = v.y;
            sW[(k + 2) * 128 + o] = v.z;
            sW[(k + 3) * 128 + o] = v.w;
        }
    }
    {
        int rl = tid & 63;
        int kh = tid >> 6;
        int r = rowBase + rl;
        bool ok = (r < n_nodes);
#pragma unroll
        for (int j = 0; j < 16; j++) {
            int k0 = kh * 64 + j * 4;
            float4 v = ok ? ((const float4*)nf)[r * 32 + (k0 >> 2)]
                          : make_float4(0.f, 0.f, 0.f, 0.f);
            nT[(k0 + 0) * NT_STRIDE + rl] = v.x;
            nT[(k0 + 1) * NT_STRIDE + rl] = v.y;
            nT[(k0 + 2) * NT_STRIDE + rl] = v.z;
            nT[(k0 + 3) * NT_STRIDE + rl] = v.w;
        }
    }
    __syncthreads();

    int tx = tid & 15;
    int ty = tid >> 4;
    float c[8][8];
#pragma unroll
    for (int i = 0; i < 8; i++)
#pragma unroll
        for (int j = 0; j < 8; j++) c[i][j] = 0.f;

#pragma unroll 4
    for (int k = 0; k < 128; k++) {
        float4 a0 = *(float4*)&nT[k * NT_STRIDE + ty * 8];
        float4 a1 = *(float4*)&nT[k * NT_STRIDE + ty * 8 + 4];
        float4 b0 = *(float4*)&sW[k * 128 + tx * 8];
        float4 b1 = *(float4*)&sW[k * 128 + tx * 8 + 4];
        float a[8] = {a0.x, a0.y, a0.z, a0.w, a1.x, a1.y, a1.z, a1.w};
        float b[8] = {b0.x, b0.y, b0.z, b0.w, b1.x, b1.y, b1.z, b1.w};
#pragma unroll
        for (int i = 0; i < 8; i++)
#pragma unroll
            for (int j = 0; j < 8; j++) c[i][j] += a[i] * b[j];
    }

#pragma unroll
    for (int i = 0; i < 8; i++) {
        int r = rowBase + ty * 8 + i;
        if (r < n_nodes) {
            ((float4*)g_z)[r * 32 + tx * 2] =
                make_float4(c[i][0], c[i][1], c[i][2], c[i][3]);
            ((float4*)g_z)[r * 32 + tx * 2 + 1] =
                make_float4(c[i][4], c[i][5], c[i][6], c[i][7]);
            __half2 p0 = __floats2half2_rn(c[i][0], c[i][1]);
            __half2 p1 = __floats2half2_rn(c[i][2], c[i][3]);
            __half2 p2 = __floats2half2_rn(c[i][4], c[i][5]);
            __half2 p3 = __floats2half2_rn(c[i][6], c[i][7]);
            uint4 hv;
            hv.x = *reinterpret_cast<unsigned*>(&p0);
            hv.y = *reinterpret_cast<unsigned*>(&p1);
            hv.z = *reinterpret_cast<unsigned*>(&p2);
            hv.w = *reinterpret_cast<unsigned*>(&p3);
            *reinterpret_cast<uint4*>(g_zh + (size_t)r * 128 + tx * 8) = hv;
        }
    }
}

// ---------------------------------------------------------------------------
// K2: s_src[n] = z[n]·a_src ; s_dst[n] = z[n]·a_dst
// ---------------------------------------------------------------------------
__global__ void k_sdot(const float* __restrict__ Wa, int n_nodes) {
    int node = (blockIdx.x * blockDim.x + threadIdx.x) >> 5;
    int lane = threadIdx.x & 31;
    if (node >= n_nodes) return;
    float4 z4 = ((const float4*)g_z)[node * 32 + lane];
    float4 as = ((const float4*)Wa)[lane];               // a_src = Wa[0:128]
    float4 ad = ((const float4*)(Wa + 160))[lane];       // a_dst = Wa[160:288]
    float v1 = z4.x * as.x + z4.y * as.y + z4.z * as.z + z4.w * as.w;
    float v2 = z4.x * ad.x + z4.y * ad.y + z4.z * ad.z + z4.w * ad.w;
    v1 = warp_sum(v1);
    v2 = warp_sum(v2);
    if (lane == 0) {
        g_ssrc[node] = v1;
        g_sdst[node] = v2;
    }
}

// ---------------------------------------------------------------------------
// K3: coalesced s_e = efeats·a_e (warp = 4 edges, 8 lanes each) + deg histogram
// ---------------------------------------------------------------------------
__global__ __launch_bounds__(256) void k_se_hist(const float* __restrict__ ef,
                                                 const float* __restrict__ Wa,
                                                 const int* __restrict__ dst,
                                                 int n_edges) {
    __shared__ float sa[32];
    if (threadIdx.x < 32) sa[threadIdx.x] = Wa[128 + threadIdx.x];  // a_e
    __syncthreads();
    int warp = (blockIdx.x * blockDim.x + threadIdx.x) >> 5;
    int lane = threadIdx.x & 31;
    int e = warp * 4 + (lane >> 3);
    int g = lane & 7;               // 8-lane group position
    float v = 0.f;
    if (e < n_edges) {
        float4 x = __ldg((const float4*)ef + (size_t)e * 8 + g);
        v = x.x * sa[g * 4] + x.y * sa[g * 4 + 1] +
            x.z * sa[g * 4 + 2] + x.w * sa[g * 4 + 3];
    }
    v += __shfl_xor_sync(0xffffffffu, v, 4);
    v += __shfl_xor_sync(0xffffffffu, v, 2);
    v += __shfl_xor_sync(0xffffffffu, v, 1);
    if (g == 0 && e < n_edges) {
        g_se[e] = v;
        atomicAdd(&g_deg[dst[e]], 1);
    }
}

// ---------------------------------------------------------------------------
// K4a/b/c: exclusive prefix scan of deg -> start/cursor
// ---------------------------------------------------------------------------
__global__ void k_scan1(int n) {
    __shared__ int s[256];
    int i = blockIdx.x * 256 + threadIdx.x;
    int v = (i < n) ? g_deg[i] : 0;
    s[threadIdx.x] = v;
    __syncthreads();
#pragma unroll
    for (int off = 1; off < 256; off <<= 1) {
        int t = (threadIdx.x >= off) ? s[threadIdx.x - off] : 0;
        __syncthreads();
        s[threadIdx.x] += t;
        __syncthreads();
    }
    if (i < n) g_start[i] = s[threadIdx.x] - v;
    if (threadIdx.x == 255) g_blocksum[blockIdx.x] = s[255];
}

__global__ void k_scan2(int nb) {
    __shared__ int s[256];
    int v = (threadIdx.x < nb) ? g_blocksum[threadIdx.x] : 0;
    s[threadIdx.x] = v;
    __syncthreads();
#pragma unroll
    for (int off = 1; off < 256; off <<= 1) {
        int t = (threadIdx.x >= off) ? s[threadIdx.x - off] : 0;
        __syncthreads();
        s[threadIdx.x] += t;
        __syncthreads();
    }
    if (threadIdx.x < nb) g_blocksum[threadIdx.x] = s[threadIdx.x] - v;
}

__global__ void k_scan3(int n) {
    int i = blockIdx.x * 256 + threadIdx.x;
    if (i < n) {
        int st = g_start[i] + g_blocksum[blockIdx.x];
        g_start[i] = st;
        g_cursor[i] = st;
    }
}

// ---------------------------------------------------------------------------
// K5: per edge: w = exp(leaky_relu(ssrc[src]+s_e+sdst[dst]));
//     place (src, w) directly into dst-sorted position (fused sort pass)
// ---------------------------------------------------------------------------
__global__ __launch_bounds__(256) void k_edge_place(const int* __restrict__ src,
                                                    const int* __restrict__ dst,
                                                    int n_edges) {
    int e = blockIdx.x * blockDim.x + threadIdx.x;
    if (e >= n_edges) return;
    int s = src[e];
    int d = dst[e];
    float ev = __ldg(&g_ssrc[s]) + g_se[e] + __ldg(&g_sdst[d]);
    ev = (ev > 0.f) ? ev : 0.01f * ev;
    float w = __expf(ev);
    int pos = atomicAdd(&g_cursor[d], 1);
    g_psrc[pos] = s;
    g_pw[pos] = w;
}

// ---------------------------------------------------------------------------
// K6: warp per dst node: h[d] = (sum_e w_e * zh[src_e]) / (sum_e w_e)
//     psrc/pw reads coalesced; zh gathers fp16 (half the L2 traffic)
// ---------------------------------------------------------------------------
__global__ __launch_bounds__(256) void k_agg(float* __restrict__ out, int n_nodes) {
    int d = (blockIdx.x * blockDim.x + threadIdx.x) >> 5;
    int lane = threadIdx.x & 31;
    if (d >= n_nodes) return;
    int start = g_start[d];
    int deg = g_cursor[d] - start;   // cursor advanced to end by k_edge_place
    float4 acc = make_float4(0.f, 0.f, 0.f, 0.f);
    float wsum = 0.f;

    for (int i = 0; i < deg; i += 32) {
        int s = 0;
        float wv = 0.f;
        if (i + lane < deg) {
            s = g_psrc[start + i + lane];
            wv = g_pw[start + i + lane];
        }
        wsum += wv;
        int cnt = min(32, deg - i);
        for (int j = 0; j < cnt; j++) {
            int sj = __shfl_sync(0xffffffffu, s, j);
            float wj = __shfl_sync(0xffffffffu, wv, j);
            uint2 hz = *reinterpret_cast<const uint2*>(g_zh + (size_t)sj * 128 + lane * 4);
            __half2 a01 = *reinterpret_cast<__half2*>(&hz.x);
            __half2 a23 = *reinterpret_cast<__half2*>(&hz.y);
            float2 f01 = __half22float2(a01);
            float2 f23 = __half22float2(a23);
            acc.x += wj * f01.x;
            acc.y += wj * f01.y;
            acc.z += wj * f23.x;
            acc.w += wj * f23.y;
        }
    }
    wsum = warp_sum(wsum);
    float dinv = (wsum > 0.f) ? 1.0f / wsum : 0.f;
    ((float4*)out)[d * 32 + lane] =
        make_float4(acc.x * dinv, acc.y * dinv, acc.z * dinv, acc.w * dinv);
}

// ---------------------------------------------------------------------------
extern "C" void kernel_launch(void* const* d_in, const int* in_sizes, int n_in,
                              void* d_out, int out_size) {
    const float* nf  = (const float*)d_in[0];
    const float* ef  = (const float*)d_in[1];
    const float* Wfc = (const float*)d_in[2];
    const float* Wa  = (const float*)d_in[3];
    const int*   src = (const int*)d_in[4];
    const int*   dst = (const int*)d_in[5];
    float* out = (float*)d_out;

    int n_nodes = in_sizes[0] / 128;
    int n_edges = in_sizes[4];
    int nscan = (n_nodes + 255) / 256;  // 196 (<= 256)

    cudaFuncSetAttribute(k_gemm, cudaFuncAttributeMaxDynamicSharedMemorySize, GEMM_SMEM);

    k_zero<<<(n_nodes + 255) / 256, 256>>>(n_nodes);
    k_gemm<<<(n_nodes + 63) / 64, 128, GEMM_SMEM>>>(nf, Wfc, n_nodes);
    k_sdot<<<(n_nodes + 7) / 8, 256>>>(Wa, n_nodes);
    k_se_hist<<<(n_edges + 31) / 32, 256>>>(ef, Wa, dst, n_edges);
    k_scan1<<<nscan, 256>>>(n_nodes);
    k_scan2<<<1, 256>>>(nscan);
    k_scan3<<<nscan, 256>>>(n_nodes);
    k_edge_place<<<(n_edges + 255) / 256, 256>>>(src, dst, n_edges);
    k_agg<<<(n_nodes + 7) / 8, 256>>>(out, n_nodes);
}

// round 4
// speedup vs baseline: 1.9855x; 1.0817x over previous
#include <cuda_runtime.h>
#include <cuda_fp16.h>

#define NMAX_NODES 50000
#define NMAX_EDGES 800000

typedef unsigned long long ull;

// Scratch (device globals; no allocation allowed)
__device__ float  g_z[NMAX_NODES * 128];
__device__ __half g_zh[NMAX_NODES * 128];
__device__ float  g_ssrc[NMAX_NODES];
__device__ float  g_sdst[NMAX_NODES];
__device__ float  g_se[NMAX_EDGES];
__device__ int    g_deg[NMAX_NODES];
__device__ int    g_start[NMAX_NODES];
__device__ int    g_cursor[NMAX_NODES];
__device__ int    g_blocksum[256];
__device__ int    g_psrc[NMAX_EDGES];
__device__ float  g_pw[NMAX_EDGES];

__device__ __forceinline__ float warp_sum(float v) {
#pragma unroll
    for (int o = 16; o; o >>= 1) v += __shfl_xor_sync(0xffffffffu, v, o);
    return v;
}

__device__ __forceinline__ ull pack2(float lo, float hi) {
    ull r;
    asm("mov.b64 %0, {%1, %2};" : "=l"(r) : "f"(lo), "f"(hi));
    return r;
}
__device__ __forceinline__ void fma2(ull& c, ull a, ull b) {
    asm("fma.rn.f32x2 %0, %1, %2, %0;" : "+l"(c) : "l"(a), "l"(b));
}

// ---------------------------------------------------------------------------
// K0: zero deg
// ---------------------------------------------------------------------------
__global__ void k_zero(int n_nodes) {
    int i = blockIdx.x * blockDim.x + threadIdx.x;
    if (i < n_nodes) g_deg[i] = 0;
}

// ---------------------------------------------------------------------------
// K1: z = nfeats @ W_fc^T  using packed fma.rn.f32x2 (2 fp32 FMA / instr)
// Block: 128 threads, tile 64 rows x 128 cols, 8x8 micro-tile per thread.
// ---------------------------------------------------------------------------
#define NT_STRIDE 72
#define GEMM_SMEM (65536 + 128 * NT_STRIDE * 4)

__global__ __launch_bounds__(128) void k_gemm(const float* __restrict__ nf,
                                              const float* __restrict__ W,
                                              int n_nodes) {
    extern __shared__ float sm[];
    float* sW = sm;              // [128][128]  sW[k*128+o] = W[o][k]
    float* nT = sm + 16384;      // [128][NT_STRIDE]
    int tid = threadIdx.x;
    int rowBase = blockIdx.x * 64;

    {
        int o = tid;
#pragma unroll
        for (int j = 0; j < 32; j++) {
            float4 v = ((const float4*)W)[o * 32 + j];
            int k = j * 4;
            sW[(k + 0) * 128 + o] = v.x;
            sW[(k + 1) * 128 + o] = v.y;
            sW[(k + 2) * 128 + o] = v.z;
            sW[(k + 3) * 128 + o] = v.w;
        }
    }
    {
        int rl = tid & 63;
        int kh = tid >> 6;
        int r = rowBase + rl;
        bool ok = (r < n_nodes);
#pragma unroll
        for (int j = 0; j < 16; j++) {
            int k0 = kh * 64 + j * 4;
            float4 v = ok ? ((const float4*)nf)[r * 32 + (k0 >> 2)]
                          : make_float4(0.f, 0.f, 0.f, 0.f);
            nT[(k0 + 0) * NT_STRIDE + rl] = v.x;
            nT[(k0 + 1) * NT_STRIDE + rl] = v.y;
            nT[(k0 + 2) * NT_STRIDE + rl] = v.z;
            nT[(k0 + 3) * NT_STRIDE + rl] = v.w;
        }
    }
    __syncthreads();

    int tx = tid & 15;
    int ty = tid >> 4;
    ull c2[8][4];   // packed accumulators: c2[i][jj] = (c[i][2jj], c[i][2jj+1])
#pragma unroll
    for (int i = 0; i < 8; i++)
#pragma unroll
        for (int j = 0; j < 4; j++) c2[i][j] = 0ull;

#pragma unroll 4
    for (int k = 0; k < 128; k++) {
        float4 a0 = *(float4*)&nT[k * NT_STRIDE + ty * 8];
        float4 a1 = *(float4*)&nT[k * NT_STRIDE + ty * 8 + 4];
        // b pairs come directly from LDS.128 register pairs (no pack needed)
        ulonglong2 bb01 = *(ulonglong2*)&sW[k * 128 + tx * 8];
        ulonglong2 bb23 = *(ulonglong2*)&sW[k * 128 + tx * 8 + 4];
        float a[8] = {a0.x, a0.y, a0.z, a0.w, a1.x, a1.y, a1.z, a1.w};
#pragma unroll
        for (int i = 0; i < 8; i++) {
            ull aa = pack2(a[i], a[i]);
            fma2(c2[i][0], aa, bb01.x);
            fma2(c2[i][1], aa, bb01.y);
            fma2(c2[i][2], aa, bb23.x);
            fma2(c2[i][3], aa, bb23.y);
        }
    }

#pragma unroll
    for (int i = 0; i < 8; i++) {
        int r = rowBase + ty * 8 + i;
        if (r < n_nodes) {
            float2 f0 = *reinterpret_cast<float2*>(&c2[i][0]);
            float2 f1 = *reinterpret_cast<float2*>(&c2[i][1]);
            float2 f2 = *reinterpret_cast<float2*>(&c2[i][2]);
            float2 f3 = *reinterpret_cast<float2*>(&c2[i][3]);
            ((float4*)g_z)[r * 32 + tx * 2] = make_float4(f0.x, f0.y, f1.x, f1.y);
            ((float4*)g_z)[r * 32 + tx * 2 + 1] = make_float4(f2.x, f2.y, f3.x, f3.y);
            __half2 p0 = __floats2half2_rn(f0.x, f0.y);
            __half2 p1 = __floats2half2_rn(f1.x, f1.y);
            __half2 p2 = __floats2half2_rn(f2.x, f2.y);
            __half2 p3 = __floats2half2_rn(f3.x, f3.y);
            uint4 hv;
            hv.x = *reinterpret_cast<unsigned*>(&p0);
            hv.y = *reinterpret_cast<unsigned*>(&p1);
            hv.z = *reinterpret_cast<unsigned*>(&p2);
            hv.w = *reinterpret_cast<unsigned*>(&p3);
            *reinterpret_cast<uint4*>(g_zh + (size_t)r * 128 + tx * 8) = hv;
        }
    }
}

// ---------------------------------------------------------------------------
// K2: s_src[n] = z[n]·a_src ; s_dst[n] = z[n]·a_dst
// ---------------------------------------------------------------------------
__global__ void k_sdot(const float* __restrict__ Wa, int n_nodes) {
    int node = (blockIdx.x * blockDim.x + threadIdx.x) >> 5;
    int lane = threadIdx.x & 31;
    if (node >= n_nodes) return;
    float4 z4 = ((const float4*)g_z)[node * 32 + lane];
    float4 as = ((const float4*)Wa)[lane];               // a_src = Wa[0:128]
    float4 ad = ((const float4*)(Wa + 160))[lane];       // a_dst = Wa[160:288]
    float v1 = z4.x * as.x + z4.y * as.y + z4.z * as.z + z4.w * as.w;
    float v2 = z4.x * ad.x + z4.y * ad.y + z4.z * ad.z + z4.w * ad.w;
    v1 = warp_sum(v1);
    v2 = warp_sum(v2);
    if (lane == 0) {
        g_ssrc[node] = v1;
        g_sdst[node] = v2;
    }
}

// ---------------------------------------------------------------------------
// K3: coalesced s_e = efeats·a_e + deg histogram.
// Warp = 16 edges in 4 independent chunks (MLP=4); 8 lanes per edge.
// ---------------------------------------------------------------------------
__global__ __launch_bounds__(256) void k_se_hist(const float* __restrict__ ef,
                                                 const float* __restrict__ Wa,
                                                 const int* __restrict__ dst,
                                                 int n_edges) {
    __shared__ float sa[32];
    if (threadIdx.x < 32) sa[threadIdx.x] = Wa[128 + threadIdx.x];  // a_e
    __syncthreads();
    int warp = (blockIdx.x * blockDim.x + threadIdx.x) >> 5;
    int lane = threadIdx.x & 31;
    int sub = lane >> 3;            // which of 4 edges in a chunk
    int g = lane & 7;               // 8-lane group position
    int e0 = warp * 16 + sub;

    float4 x[4];
#pragma unroll
    for (int u = 0; u < 4; u++) {
        int e = e0 + u * 4;
        x[u] = (e < n_edges) ? __ldg((const float4*)ef + (size_t)e * 8 + g)
                             : make_float4(0.f, 0.f, 0.f, 0.f);
    }
    float c0 = sa[g * 4], c1 = sa[g * 4 + 1], c2 = sa[g * 4 + 2], c3 = sa[g * 4 + 3];
    float v[4];
#pragma unroll
    for (int u = 0; u < 4; u++)
        v[u] = x[u].x * c0 + x[u].y * c1 + x[u].z * c2 + x[u].w * c3;
#pragma unroll
    for (int u = 0; u < 4; u++) {
        v[u] += __shfl_xor_sync(0xffffffffu, v[u], 4);
        v[u] += __shfl_xor_sync(0xffffffffu, v[u], 2);
        v[u] += __shfl_xor_sync(0xffffffffu, v[u], 1);
    }
    if (g == 0) {
#pragma unroll
        for (int u = 0; u < 4; u++) {
            int e = e0 + u * 4;
            if (e < n_edges) {
                g_se[e] = v[u];
                atomicAdd(&g_deg[dst[e]], 1);
            }
        }
    }
}

// ---------------------------------------------------------------------------
// K4a/b/c: exclusive prefix scan of deg -> start/cursor
// ---------------------------------------------------------------------------
__global__ void k_scan1(int n) {
    __shared__ int s[256];
    int i = blockIdx.x * 256 + threadIdx.x;
    int v = (i < n) ? g_deg[i] : 0;
    s[threadIdx.x] = v;
    __syncthreads();
#pragma unroll
    for (int off = 1; off < 256; off <<= 1) {
        int t = (threadIdx.x >= off) ? s[threadIdx.x - off] : 0;
        __syncthreads();
        s[threadIdx.x] += t;
        __syncthreads();
    }
    if (i < n) g_start[i] = s[threadIdx.x] - v;
    if (threadIdx.x == 255) g_blocksum[blockIdx.x] = s[255];
}

__global__ void k_scan2(int nb) {
    __shared__ int s[256];
    int v = (threadIdx.x < nb) ? g_blocksum[threadIdx.x] : 0;
    s[threadIdx.x] = v;
    __syncthreads();
#pragma unroll
    for (int off = 1; off < 256; off <<= 1) {
        int t = (threadIdx.x >= off) ? s[threadIdx.x - off] : 0;
        __syncthreads();
        s[threadIdx.x] += t;
        __syncthreads();
    }
    if (threadIdx.x < nb) g_blocksum[threadIdx.x] = s[threadIdx.x] - v;
}

__global__ void k_scan3(int n) {
    int i = blockIdx.x * 256 + threadIdx.x;
    if (i < n) {
        int st = g_start[i] + g_blocksum[blockIdx.x];
        g_start[i] = st;
        g_cursor[i] = st;
    }
}

// ---------------------------------------------------------------------------
// K5: per edge: w = exp(leaky_relu(ssrc[src]+s_e+sdst[dst]));
//     place (src, w) directly into dst-sorted position (fused sort pass)
// ---------------------------------------------------------------------------
__global__ __launch_bounds__(256) void k_edge_place(const int* __restrict__ src,
                                                    const int* __restrict__ dst,
                                                    int n_edges) {
    int e = blockIdx.x * blockDim.x + threadIdx.x;
    if (e >= n_edges) return;
    int s = src[e];
    int d = dst[e];
    float ev = __ldg(&g_ssrc[s]) + g_se[e] + __ldg(&g_sdst[d]);
    ev = (ev > 0.f) ? ev : 0.01f * ev;
    float w = __expf(ev);
    int pos = atomicAdd(&g_cursor[d], 1);
    g_psrc[pos] = s;
    g_pw[pos] = w;
}

// ---------------------------------------------------------------------------
// K6: warp per dst node: h[d] = (sum_e w_e * zh[src_e]) / (sum_e w_e)
// ---------------------------------------------------------------------------
__global__ __launch_bounds__(256) void k_agg(float* __restrict__ out, int n_nodes) {
    int d = (blockIdx.x * blockDim.x + threadIdx.x) >> 5;
    int lane = threadIdx.x & 31;
    if (d >= n_nodes) return;
    int start = g_start[d];
    int deg = g_cursor[d] - start;   // cursor advanced to end by k_edge_place
    float4 acc = make_float4(0.f, 0.f, 0.f, 0.f);
    float wsum = 0.f;

    for (int i = 0; i < deg; i += 32) {
        int s = 0;
        float wv = 0.f;
        if (i + lane < deg) {
            s = g_psrc[start + i + lane];
            wv = g_pw[start + i + lane];
        }
        wsum += wv;
        int cnt = min(32, deg - i);
        for (int j = 0; j < cnt; j++) {
            int sj = __shfl_sync(0xffffffffu, s, j);
            float wj = __shfl_sync(0xffffffffu, wv, j);
            uint2 hz = *reinterpret_cast<const uint2*>(g_zh + (size_t)sj * 128 + lane * 4);
            __half2 a01 = *reinterpret_cast<__half2*>(&hz.x);
            __half2 a23 = *reinterpret_cast<__half2*>(&hz.y);
            float2 f01 = __half22float2(a01);
            float2 f23 = __half22float2(a23);
            acc.x += wj * f01.x;
            acc.y += wj * f01.y;
            acc.z += wj * f23.x;
            acc.w += wj * f23.y;
        }
    }
    wsum = warp_sum(wsum);
    float dinv = (wsum > 0.f) ? 1.0f / wsum : 0.f;
    ((float4*)out)[d * 32 + lane] =
        make_float4(acc.x * dinv, acc.y * dinv, acc.z * dinv, acc.w * dinv);
}

// ---------------------------------------------------------------------------
extern "C" void kernel_launch(void* const* d_in, const int* in_sizes, int n_in,
                              void* d_out, int out_size) {
    const float* nf  = (const float*)d_in[0];
    const float* ef  = (const float*)d_in[1];
    const float* Wfc = (const float*)d_in[2];
    const float* Wa  = (const float*)d_in[3];
    const int*   src = (const int*)d_in[4];
    const int*   dst = (const int*)d_in[5];
    float* out = (float*)d_out;

    int n_nodes = in_sizes[0] / 128;
    int n_edges = in_sizes[4];
    int nscan = (n_nodes + 255) / 256;  // 196 (<= 256)

    cudaFuncSetAttribute(k_gemm, cudaFuncAttributeMaxDynamicSharedMemorySize, GEMM_SMEM);

    k_zero<<<(n_nodes + 255) / 256, 256>>>(n_nodes);
    k_gemm<<<(n_nodes + 63) / 64, 128, GEMM_SMEM>>>(nf, Wfc, n_nodes);
    k_sdot<<<(n_nodes + 7) / 8, 256>>>(Wa, n_nodes);
    k_se_hist<<<(n_edges + 127) / 128, 256>>>(ef, Wa, dst, n_edges);
    k_scan1<<<nscan, 256>>>(n_nodes);
    k_scan2<<<1, 256>>>(nscan);
    k_scan3<<<nscan, 256>>>(n_nodes);
    k_edge_place<<<(n_edges + 255) / 256, 256>>>(src, dst, n_edges);
    k_agg<<<(n_nodes + 7) / 8, 256>>>(out, n_nodes);
}

// round 5
// speedup vs baseline: 2.1019x; 1.0586x over previous
#include <cuda_runtime.h>
#include <cuda_fp16.h>

#define NMAX_NODES 50000
#define NMAX_EDGES 800000

// Scratch (device globals; no allocation allowed)
__device__ __half g_zh[NMAX_NODES * 128];
__device__ __half g_nfh[NMAX_NODES * 128];
__device__ __half g_Wh[128 * 128];
__device__ float  g_ssrc[NMAX_NODES];
__device__ float  g_sdst[NMAX_NODES];
__device__ float  g_se[NMAX_EDGES];
__device__ int    g_deg[NMAX_NODES];
__device__ int    g_start[NMAX_NODES];
__device__ int    g_cursor[NMAX_NODES];
__device__ int    g_blocksum[256];
__device__ int    g_psrc[NMAX_EDGES];
__device__ float  g_pw[NMAX_EDGES];

__device__ __forceinline__ float warp_sum(float v) {
#pragma unroll
    for (int o = 16; o; o >>= 1) v += __shfl_xor_sync(0xffffffffu, v, o);
    return v;
}

__device__ __forceinline__ unsigned smem_u32(const void* p) {
    unsigned a;
    asm("{ .reg .u64 t; cvta.to.shared.u64 t, %1; cvt.u32.u64 %0, t; }"
        : "=r"(a) : "l"(p));
    return a;
}

__device__ __forceinline__ void ldsm_x4(unsigned& r0, unsigned& r1, unsigned& r2,
                                        unsigned& r3, unsigned addr) {
    asm volatile("ldmatrix.sync.aligned.m8n8.x4.shared.b16 {%0,%1,%2,%3}, [%4];"
                 : "=r"(r0), "=r"(r1), "=r"(r2), "=r"(r3) : "r"(addr));
}
__device__ __forceinline__ void ldsm_x2(unsigned& r0, unsigned& r1, unsigned addr) {
    asm volatile("ldmatrix.sync.aligned.m8n8.x2.shared.b16 {%0,%1}, [%2];"
                 : "=r"(r0), "=r"(r1) : "r"(addr));
}
__device__ __forceinline__ void mma16816(float* c, const unsigned* a, const unsigned* b) {
    asm volatile(
        "mma.sync.aligned.m16n8k16.row.col.f32.f16.f16.f32 "
        "{%0,%1,%2,%3}, {%4,%5,%6,%7}, {%8,%9}, {%0,%1,%2,%3};"
        : "+f"(c[0]), "+f"(c[1]), "+f"(c[2]), "+f"(c[3])
        : "r"(a[0]), "r"(a[1]), "r"(a[2]), "r"(a[3]), "r"(b[0]), "r"(b[1]));
}

// ---------------------------------------------------------------------------
// K0: zero deg
// ---------------------------------------------------------------------------
__global__ void k_zero(int n_nodes) {
    int i = blockIdx.x * blockDim.x + threadIdx.x;
    if (i < n_nodes) g_deg[i] = 0;
}

// ---------------------------------------------------------------------------
// K0b: convert W and nfeats to fp16
// ---------------------------------------------------------------------------
__global__ void k_tohalf(const float* __restrict__ nf, const float* __restrict__ W,
                         int n_total4) {
    int i = blockIdx.x * blockDim.x + threadIdx.x;  // one float4 per thread
    if (i >= n_total4) return;
    int base = i * 4;
    if (base < 16384) {
        float4 v = ((const float4*)W)[i];
        __half2 h0 = __floats2half2_rn(v.x, v.y);
        __half2 h1 = __floats2half2_rn(v.z, v.w);
        uint2 u;
        u.x = *reinterpret_cast<unsigned*>(&h0);
        u.y = *reinterpret_cast<unsigned*>(&h1);
        *reinterpret_cast<uint2*>(g_Wh + base) = u;
    } else {
        int j = i - 4096;  // float4 index into nf
        float4 v = ((const float4*)nf)[j];
        __half2 h0 = __floats2half2_rn(v.x, v.y);
        __half2 h1 = __floats2half2_rn(v.z, v.w);
        uint2 u;
        u.x = *reinterpret_cast<unsigned*>(&h0);
        u.y = *reinterpret_cast<unsigned*>(&h1);
        *reinterpret_cast<uint2*>(g_nfh + (size_t)j * 4) = u;
    }
}

// ---------------------------------------------------------------------------
// K1: z = nfeats @ W_fc^T via HMMA (mma.sync m16n8k16, fp16 in, fp32 acc).
// Block 256 thr (8 warps), tile 128 rows; warp w owns rows [16w,16w+16), all N.
// Writes fp16 z only (g_zh).
// ---------------------------------------------------------------------------
#define ASTR 136                 // padded row stride in halfs (272B, conflict-free)
#define GEMMH_SMEM (2 * 128 * ASTR * 2)

__global__ __launch_bounds__(256) void k_gemm_h(int n_nodes) {
    extern __shared__ __half hsm[];
    __half* sA = hsm;             // [128][ASTR]
    __half* sB = hsm + 128 * ASTR;
    int tid = threadIdx.x;
    int rowBase = blockIdx.x * 128;

    // Load A tile (guarded) and full W, 16B chunks: 2048 chunks each, 8/thread
#pragma unroll
    for (int c = tid; c < 2048; c += 256) {
        int row = c >> 4;
        int col16 = c & 15;
        uint4 v;
        int r = rowBase + row;
        if (r < n_nodes)
            v = *reinterpret_cast<const uint4*>(g_nfh + (size_t)r * 128 + col16 * 8);
        else
            v = make_uint4(0u, 0u, 0u, 0u);
        *reinterpret_cast<uint4*>(sA + row * ASTR + col16 * 8) = v;
        uint4 w = *reinterpret_cast<const uint4*>(g_Wh + row * 128 + col16 * 8);
        *reinterpret_cast<uint4*>(sB + row * ASTR + col16 * 8) = w;
    }
    __syncthreads();

    int warp = tid >> 5;
    int lane = tid & 31;
    int m0 = warp * 16;

    float acc[16][4];
#pragma unroll
    for (int nt = 0; nt < 16; nt++)
#pragma unroll
        for (int j = 0; j < 4; j++) acc[nt][j] = 0.f;

    // A ldmatrix address: row = m0 + (lane&15), k offset (lane>>4)*8
    unsigned aBase = smem_u32(sA) + ((m0 + (lane & 15)) * ASTR + ((lane >> 4) << 3)) * 2;
    // B ldmatrix address (x2, lanes 0-15 meaningful; others mirror):
    // n = nt*8 + (lane&7), k offset ((lane>>3)&1)*8
    unsigned bBase = smem_u32(sB) + ((lane & 7) * ASTR + (((lane >> 3) & 1) << 3)) * 2;

#pragma unroll
    for (int ks = 0; ks < 8; ks++) {
        unsigned a[4];
        ldsm_x4(a[0], a[1], a[2], a[3], aBase + ks * 32);  // k0=16*ks halfs = 32B
#pragma unroll
        for (int nt = 0; nt < 16; nt++) {
            unsigned b[2];
            ldsm_x2(b[0], b[1], bBase + (nt * 8 * ASTR) * 2 + ks * 32);
            mma16816(acc[nt], a, b);
        }
    }

    // Epilogue: thread holds (row m0+lane/4, col (lane&3)*2) and (+8 row) per nt
    int gr = lane >> 2;
    int colq = (lane & 3) * 2;
#pragma unroll
    for (int nt = 0; nt < 16; nt++) {
        int r0 = rowBase + m0 + gr;
        int r1 = r0 + 8;
        int col = nt * 8 + colq;
        if (r0 < n_nodes) {
            __half2 h = __floats2half2_rn(acc[nt][0], acc[nt][1]);
            *reinterpret_cast<unsigned*>(g_zh + (size_t)r0 * 128 + col) =
                *reinterpret_cast<unsigned*>(&h);
        }
        if (r1 < n_nodes) {
            __half2 h = __floats2half2_rn(acc[nt][2], acc[nt][3]);
            *reinterpret_cast<unsigned*>(g_zh + (size_t)r1 * 128 + col) =
                *reinterpret_cast<unsigned*>(&h);
        }
    }
}

// ---------------------------------------------------------------------------
// K2: s_src[n] = z[n]·a_src ; s_dst[n] = z[n]·a_dst   (reads fp16 z)
// ---------------------------------------------------------------------------
__global__ void k_sdot(const float* __restrict__ Wa, int n_nodes) {
    int node = (blockIdx.x * blockDim.x + threadIdx.x) >> 5;
    int lane = threadIdx.x & 31;
    if (node >= n_nodes) return;
    uint2 hz = *reinterpret_cast<const uint2*>(g_zh + (size_t)node * 128 + lane * 4);
    __half2 a01 = *reinterpret_cast<__half2*>(&hz.x);
    __half2 a23 = *reinterpret_cast<__half2*>(&hz.y);
    float2 f01 = __half22float2(a01);
    float2 f23 = __half22float2(a23);
    float4 as = ((const float4*)Wa)[lane];               // a_src = Wa[0:128]
    float4 ad = ((const float4*)(Wa + 160))[lane];       // a_dst = Wa[160:288]
    float v1 = f01.x * as.x + f01.y * as.y + f23.x * as.z + f23.y * as.w;
    float v2 = f01.x * ad.x + f01.y * ad.y + f23.x * ad.z + f23.y * ad.w;
    v1 = warp_sum(v1);
    v2 = warp_sum(v2);
    if (lane == 0) {
        g_ssrc[node] = v1;
        g_sdst[node] = v2;
    }
}

// ---------------------------------------------------------------------------
// K3: coalesced s_e = efeats·a_e + deg histogram (MLP=4)
// ---------------------------------------------------------------------------
__global__ __launch_bounds__(256) void k_se_hist(const float* __restrict__ ef,
                                                 const float* __restrict__ Wa,
                                                 const int* __restrict__ dst,
                                                 int n_edges) {
    __shared__ float sa[32];
    if (threadIdx.x < 32) sa[threadIdx.x] = Wa[128 + threadIdx.x];  // a_e
    __syncthreads();
    int warp = (blockIdx.x * blockDim.x + threadIdx.x) >> 5;
    int lane = threadIdx.x & 31;
    int sub = lane >> 3;
    int g = lane & 7;
    int e0 = warp * 16 + sub;

    float4 x[4];
#pragma unroll
    for (int u = 0; u < 4; u++) {
        int e = e0 + u * 4;
        x[u] = (e < n_edges) ? __ldg((const float4*)ef + (size_t)e * 8 + g)
                             : make_float4(0.f, 0.f, 0.f, 0.f);
    }
    float c0 = sa[g * 4], c1 = sa[g * 4 + 1], c2 = sa[g * 4 + 2], c3 = sa[g * 4 + 3];
    float v[4];
#pragma unroll
    for (int u = 0; u < 4; u++)
        v[u] = x[u].x * c0 + x[u].y * c1 + x[u].z * c2 + x[u].w * c3;
#pragma unroll
    for (int u = 0; u < 4; u++) {
        v[u] += __shfl_xor_sync(0xffffffffu, v[u], 4);
        v[u] += __shfl_xor_sync(0xffffffffu, v[u], 2);
        v[u] += __shfl_xor_sync(0xffffffffu, v[u], 1);
    }
    if (g == 0) {
#pragma unroll
        for (int u = 0; u < 4; u++) {
            int e = e0 + u * 4;
            if (e < n_edges) {
                g_se[e] = v[u];
                atomicAdd(&g_deg[dst[e]], 1);
            }
        }
    }
}

// ---------------------------------------------------------------------------
// K4a/b/c: exclusive prefix scan of deg -> start/cursor
// ---------------------------------------------------------------------------
__global__ void k_scan1(int n) {
    __shared__ int s[256];
    int i = blockIdx.x * 256 + threadIdx.x;
    int v = (i < n) ? g_deg[i] : 0;
    s[threadIdx.x] = v;
    __syncthreads();
#pragma unroll
    for (int off = 1; off < 256; off <<= 1) {
        int t = (threadIdx.x >= off) ? s[threadIdx.x - off] : 0;
        __syncthreads();
        s[threadIdx.x] += t;
        __syncthreads();
    }
    if (i < n) g_start[i] = s[threadIdx.x] - v;
    if (threadIdx.x == 255) g_blocksum[blockIdx.x] = s[255];
}

__global__ void k_scan2(int nb) {
    __shared__ int s[256];
    int v = (threadIdx.x < nb) ? g_blocksum[threadIdx.x] : 0;
    s[threadIdx.x] = v;
    __syncthreads();
#pragma unroll
    for (int off = 1; off < 256; off <<= 1) {
        int t = (threadIdx.x >= off) ? s[threadIdx.x - off] : 0;
        __syncthreads();
        s[threadIdx.x] += t;
        __syncthreads();
    }
    if (threadIdx.x < nb) g_blocksum[threadIdx.x] = s[threadIdx.x] - v;
}

__global__ void k_scan3(int n) {
    int i = blockIdx.x * 256 + threadIdx.x;
    if (i < n) {
        int st = g_start[i] + g_blocksum[blockIdx.x];
        g_start[i] = st;
        g_cursor[i] = st;
    }
}

// ---------------------------------------------------------------------------
// K5: per edge: w = exp(leaky_relu(ssrc[src]+s_e+sdst[dst]));
//     place (src, w) directly into dst-sorted position
// ---------------------------------------------------------------------------
__global__ __launch_bounds__(256) void k_edge_place(const int* __restrict__ src,
                                                    const int* __restrict__ dst,
                                                    int n_edges) {
    int e = blockIdx.x * blockDim.x + threadIdx.x;
    if (e >= n_edges) return;
    int s = src[e];
    int d = dst[e];
    float ev = __ldg(&g_ssrc[s]) + g_se[e] + __ldg(&g_sdst[d]);
    ev = (ev > 0.f) ? ev : 0.01f * ev;
    float w = __expf(ev);
    int pos = atomicAdd(&g_cursor[d], 1);
    g_psrc[pos] = s;
    g_pw[pos] = w;
}

// ---------------------------------------------------------------------------
// K6: warp per dst node: h[d] = (sum_e w_e * zh[src_e]) / (sum_e w_e)
// ---------------------------------------------------------------------------
__global__ __launch_bounds__(256) void k_agg(float* __restrict__ out, int n_nodes) {
    int d = (blockIdx.x * blockDim.x + threadIdx.x) >> 5;
    int lane = threadIdx.x & 31;
    if (d >= n_nodes) return;
    int start = g_start[d];
    int deg = g_cursor[d] - start;
    float4 acc = make_float4(0.f, 0.f, 0.f, 0.f);
    float wsum = 0.f;

    for (int i = 0; i < deg; i += 32) {
        int s = 0;
        float wv = 0.f;
        if (i + lane < deg) {
            s = g_psrc[start + i + lane];
            wv = g_pw[start + i + lane];
        }
        wsum += wv;
        int cnt = min(32, deg - i);
        for (int j = 0; j < cnt; j++) {
            int sj = __shfl_sync(0xffffffffu, s, j);
            float wj = __shfl_sync(0xffffffffu, wv, j);
            uint2 hz = *reinterpret_cast<const uint2*>(g_zh + (size_t)sj * 128 + lane * 4);
            __half2 a01 = *reinterpret_cast<__half2*>(&hz.x);
            __half2 a23 = *reinterpret_cast<__half2*>(&hz.y);
            float2 f01 = __half22float2(a01);
            float2 f23 = __half22float2(a23);
            acc.x += wj * f01.x;
            acc.y += wj * f01.y;
            acc.z += wj * f23.x;
            acc.w += wj * f23.y;
        }
    }
    wsum = warp_sum(wsum);
    float dinv = (wsum > 0.f) ? 1.0f / wsum : 0.f;
    ((float4*)out)[d * 32 + lane] =
        make_float4(acc.x * dinv, acc.y * dinv, acc.z * dinv, acc.w * dinv);
}

// ---------------------------------------------------------------------------
extern "C" void kernel_launch(void* const* d_in, const int* in_sizes, int n_in,
                              void* d_out, int out_size) {
    const float* nf  = (const float*)d_in[0];
    const float* ef  = (const float*)d_in[1];
    const float* Wfc = (const float*)d_in[2];
    const float* Wa  = (const float*)d_in[3];
    const int*   src = (const int*)d_in[4];
    const int*   dst = (const int*)d_in[5];
    float* out = (float*)d_out;

    int n_nodes = in_sizes[0] / 128;
    int n_edges = in_sizes[4];
    int nscan = (n_nodes + 255) / 256;  // 196 (<= 256)

    cudaFuncSetAttribute(k_gemm_h, cudaFuncAttributeMaxDynamicSharedMemorySize, GEMMH_SMEM);

    int n_total4 = (16384 + n_nodes * 128) / 4;
    k_zero<<<(n_nodes + 255) / 256, 256>>>(n_nodes);
    k_tohalf<<<(n_total4 + 255) / 256, 256>>>(nf, Wfc, n_total4);
    k_gemm_h<<<(n_nodes + 127) / 128, 256, GEMMH_SMEM>>>(n_nodes);
    k_sdot<<<(n_nodes + 7) / 8, 256>>>(Wa, n_nodes);
    k_se_hist<<<(n_edges + 127) / 128, 256>>>(ef, Wa, dst, n_edges);
    k_scan1<<<nscan, 256>>>(n_nodes);
    k_scan2<<<1, 256>>>(nscan);
    k_scan3<<<nscan, 256>>>(n_nodes);
    k_edge_place<<<(n_edges + 255) / 256, 256>>>(src, dst, n_edges);
    k_agg<<<(n_nodes + 7) / 8, 256>>>(out, n_nodes);
}

// round 6
// speedup vs baseline: 3.3170x; 1.5781x over previous
#include <cuda_runtime.h>
#include <cuda_fp16.h>

#define NMAX_NODES 50000
#define NMAX_EDGES 800000

// Scratch (device globals; no allocation allowed)
__device__ __half g_zh[NMAX_NODES * 128];
__device__ float  g_ssrc[NMAX_NODES];
__device__ float  g_sdst[NMAX_NODES];
__device__ float  g_se[NMAX_EDGES];
__device__ int    g_deg[NMAX_NODES];
__device__ int    g_start[NMAX_NODES];
__device__ int    g_cursor[NMAX_NODES];
__device__ int    g_blocksum[256];
__device__ uint2  g_pe[NMAX_EDGES];   // packed (src, ssrc[src]+s_e)

__device__ __forceinline__ float warp_sum(float v) {
#pragma unroll
    for (int o = 16; o; o >>= 1) v += __shfl_xor_sync(0xffffffffu, v, o);
    return v;
}

__device__ __forceinline__ unsigned smem_u32(const void* p) {
    unsigned a;
    asm("{ .reg .u64 t; cvta.to.shared.u64 t, %1; cvt.u32.u64 %0, t; }"
        : "=r"(a) : "l"(p));
    return a;
}

__device__ __forceinline__ void ldsm_x4(unsigned& r0, unsigned& r1, unsigned& r2,
                                        unsigned& r3, unsigned addr) {
    asm volatile("ldmatrix.sync.aligned.m8n8.x4.shared.b16 {%0,%1,%2,%3}, [%4];"
                 : "=r"(r0), "=r"(r1), "=r"(r2), "=r"(r3) : "r"(addr));
}
__device__ __forceinline__ void ldsm_x2(unsigned& r0, unsigned& r1, unsigned addr) {
    asm volatile("ldmatrix.sync.aligned.m8n8.x2.shared.b16 {%0,%1}, [%2];"
                 : "=r"(r0), "=r"(r1) : "r"(addr));
}
__device__ __forceinline__ void mma16816(float* c, const unsigned* a, const unsigned* b) {
    asm volatile(
        "mma.sync.aligned.m16n8k16.row.col.f32.f16.f16.f32 "
        "{%0,%1,%2,%3}, {%4,%5,%6,%7}, {%8,%9}, {%0,%1,%2,%3};"
        : "+f"(c[0]), "+f"(c[1]), "+f"(c[2]), "+f"(c[3])
        : "r"(a[0]), "r"(a[1]), "r"(a[2]), "r"(a[3]), "r"(b[0]), "r"(b[1]));
}

__device__ __forceinline__ unsigned pack_h2(float a, float b) {
    __half2 h = __floats2half2_rn(a, b);
    return *reinterpret_cast<unsigned*>(&h);
}

// ---------------------------------------------------------------------------
// K0: zero deg
// ---------------------------------------------------------------------------
__global__ void k_zero(int n_nodes) {
    int i = blockIdx.x * blockDim.x + threadIdx.x;
    if (i < n_nodes) g_deg[i] = 0;
}

// ---------------------------------------------------------------------------
// K1: z = nfeats @ W_fc^T via HMMA, fp32 inputs converted inline.
// Fused epilogue: writes fp16 z AND s_src/s_dst dot products.
// Block 256 thr (8 warps), tile 128 rows; warp w owns rows [16w,16w+16).
// ---------------------------------------------------------------------------
#define ASTR 136                 // padded row stride in halfs
#define GEMMH_SMEM (2 * 128 * ASTR * 2 + 288 * 4)

__global__ __launch_bounds__(256) void k_gemm_h(const float* __restrict__ nf,
                                                const float* __restrict__ W,
                                                const float* __restrict__ Wa,
                                                int n_nodes) {
    extern __shared__ __half hsm[];
    __half* sA = hsm;             // [128][ASTR]
    __half* sB = hsm + 128 * ASTR;
    float* sWa = reinterpret_cast<float*>(hsm + 2 * 128 * ASTR);  // [288]
    int tid = threadIdx.x;
    int rowBase = blockIdx.x * 128;

    if (tid < 144) {
        ((float2*)sWa)[tid] = ((const float2*)Wa)[tid];  // 288 floats
    }
    // Stage A tile (fp32->fp16 inline, guarded) and W (converted per block)
#pragma unroll
    for (int c = tid; c < 2048; c += 256) {
        int row = c >> 4;
        int col16 = c & 15;                 // 8-half chunk
        int r = rowBase + row;
        uint4 hv = make_uint4(0u, 0u, 0u, 0u);
        if (r < n_nodes) {
            float4 v0 = ((const float4*)nf)[(size_t)r * 32 + col16 * 2];
            float4 v1 = ((const float4*)nf)[(size_t)r * 32 + col16 * 2 + 1];
            hv.x = pack_h2(v0.x, v0.y);
            hv.y = pack_h2(v0.z, v0.w);
            hv.z = pack_h2(v1.x, v1.y);
            hv.w = pack_h2(v1.z, v1.w);
        }
        *reinterpret_cast<uint4*>(sA + row * ASTR + col16 * 8) = hv;
        float4 w0 = ((const float4*)W)[row * 32 + col16 * 2];
        float4 w1 = ((const float4*)W)[row * 32 + col16 * 2 + 1];
        uint4 wv;
        wv.x = pack_h2(w0.x, w0.y);
        wv.y = pack_h2(w0.z, w0.w);
        wv.z = pack_h2(w1.x, w1.y);
        wv.w = pack_h2(w1.z, w1.w);
        *reinterpret_cast<uint4*>(sB + row * ASTR + col16 * 8) = wv;
    }
    __syncthreads();

    int warp = tid >> 5;
    int lane = tid & 31;
    int m0 = warp * 16;

    float acc[16][4];
#pragma unroll
    for (int nt = 0; nt < 16; nt++)
#pragma unroll
        for (int j = 0; j < 4; j++) acc[nt][j] = 0.f;

    unsigned aBase = smem_u32(sA) + ((m0 + (lane & 15)) * ASTR + ((lane >> 4) << 3)) * 2;
    unsigned bBase = smem_u32(sB) + ((lane & 7) * ASTR + (((lane >> 3) & 1) << 3)) * 2;

#pragma unroll
    for (int ks = 0; ks < 8; ks++) {
        unsigned a[4];
        ldsm_x4(a[0], a[1], a[2], a[3], aBase + ks * 32);
#pragma unroll
        for (int nt = 0; nt < 16; nt++) {
            unsigned b[2];
            ldsm_x2(b[0], b[1], bBase + (nt * 8 * ASTR) * 2 + ks * 32);
            mma16816(acc[nt], a, b);
        }
    }

    // Epilogue: z (fp16) + fused s_src/s_dst partial dots
    int gr = lane >> 2;
    int colq = (lane & 3) * 2;
    int r0 = rowBase + m0 + gr;
    int r1 = r0 + 8;
    float v1a = 0.f, v2a = 0.f, v1b = 0.f, v2b = 0.f;
#pragma unroll
    for (int nt = 0; nt < 16; nt++) {
        int col = nt * 8 + colq;
        float as0 = sWa[col], as1 = sWa[col + 1];
        float ad0 = sWa[160 + col], ad1 = sWa[161 + col];
        v1a += acc[nt][0] * as0 + acc[nt][1] * as1;
        v2a += acc[nt][0] * ad0 + acc[nt][1] * ad1;
        v1b += acc[nt][2] * as0 + acc[nt][3] * as1;
        v2b += acc[nt][2] * ad0 + acc[nt][3] * ad1;
        if (r0 < n_nodes) {
            unsigned h = pack_h2(acc[nt][0], acc[nt][1]);
            *reinterpret_cast<unsigned*>(g_zh + (size_t)r0 * 128 + col) = h;
        }
        if (r1 < n_nodes) {
            unsigned h = pack_h2(acc[nt][2], acc[nt][3]);
            *reinterpret_cast<unsigned*>(g_zh + (size_t)r1 * 128 + col) = h;
        }
    }
    // quad reduce (lanes sharing gr): xor 1, 2
#pragma unroll
    for (int o = 1; o <= 2; o <<= 1) {
        v1a += __shfl_xor_sync(0xffffffffu, v1a, o);
        v2a += __shfl_xor_sync(0xffffffffu, v2a, o);
        v1b += __shfl_xor_sync(0xffffffffu, v1b, o);
        v2b += __shfl_xor_sync(0xffffffffu, v2b, o);
    }
    if ((lane & 3) == 0) {
        if (r0 < n_nodes) { g_ssrc[r0] = v1a; g_sdst[r0] = v2a; }
        if (r1 < n_nodes) { g_ssrc[r1] = v1b; g_sdst[r1] = v2b; }
    }
}

// ---------------------------------------------------------------------------
// K2: coalesced s_e = efeats·a_e + deg histogram. Warp = 32 edges (MLP=8).
// ---------------------------------------------------------------------------
__global__ __launch_bounds__(256) void k_se_hist(const float* __restrict__ ef,
                                                 const float* __restrict__ Wa,
                                                 const int* __restrict__ dst,
                                                 int n_edges) {
    __shared__ float sa[32];
    if (threadIdx.x < 32) sa[threadIdx.x] = Wa[128 + threadIdx.x];  // a_e
    __syncthreads();
    int warp = (blockIdx.x * blockDim.x + threadIdx.x) >> 5;
    int lane = threadIdx.x & 31;
    int sub = lane >> 3;
    int g = lane & 7;
    int e0 = warp * 32 + sub;

    float4 x[8];
#pragma unroll
    for (int u = 0; u < 8; u++) {
        int e = e0 + u * 4;
        x[u] = (e < n_edges) ? __ldg((const float4*)ef + (size_t)e * 8 + g)
                             : make_float4(0.f, 0.f, 0.f, 0.f);
    }
    float c0 = sa[g * 4], c1 = sa[g * 4 + 1], c2 = sa[g * 4 + 2], c3 = sa[g * 4 + 3];
    float v[8];
#pragma unroll
    for (int u = 0; u < 8; u++)
        v[u] = x[u].x * c0 + x[u].y * c1 + x[u].z * c2 + x[u].w * c3;
#pragma unroll
    for (int u = 0; u < 8; u++) {
        v[u] += __shfl_xor_sync(0xffffffffu, v[u], 4);
        v[u] += __shfl_xor_sync(0xffffffffu, v[u], 2);
        v[u] += __shfl_xor_sync(0xffffffffu, v[u], 1);
    }
    if (g == 0) {
#pragma unroll
        for (int u = 0; u < 8; u++) {
            int e = e0 + u * 4;
            if (e < n_edges) {
                g_se[e] = v[u];
                atomicAdd(&g_deg[dst[e]], 1);
            }
        }
    }
}

// ---------------------------------------------------------------------------
// K3a/b/c: exclusive prefix scan of deg -> start/cursor
// ---------------------------------------------------------------------------
__global__ void k_scan1(int n) {
    __shared__ int s[256];
    int i = blockIdx.x * 256 + threadIdx.x;
    int v = (i < n) ? g_deg[i] : 0;
    s[threadIdx.x] = v;
    __syncthreads();
#pragma unroll
    for (int off = 1; off < 256; off <<= 1) {
        int t = (threadIdx.x >= off) ? s[threadIdx.x - off] : 0;
        __syncthreads();
        s[threadIdx.x] += t;
        __syncthreads();
    }
    if (i < n) g_start[i] = s[threadIdx.x] - v;
    if (threadIdx.x == 255) g_blocksum[blockIdx.x] = s[255];
}

__global__ void k_scan2(int nb) {
    __shared__ int s[256];
    int v = (threadIdx.x < nb) ? g_blocksum[threadIdx.x] : 0;
    s[threadIdx.x] = v;
    __syncthreads();
#pragma unroll
    for (int off = 1; off < 256; off <<= 1) {
        int t = (threadIdx.x >= off) ? s[threadIdx.x - off] : 0;
        __syncthreads();
        s[threadIdx.x] += t;
        __syncthreads();
    }
    if (threadIdx.x < nb) g_blocksum[threadIdx.x] = s[threadIdx.x] - v;
}

__global__ void k_scan3(int n) {
    int i = blockIdx.x * 256 + threadIdx.x;
    if (i < n) {
        int st = g_start[i] + g_blocksum[blockIdx.x];
        g_start[i] = st;
        g_cursor[i] = st;
    }
}

// ---------------------------------------------------------------------------
// K4: per edge: t = ssrc[src] + s_e; place packed (src, t) into dst-sorted
//     position. (exp/leaky/sdst deferred to k_agg, where sdst is uniform.)
// ---------------------------------------------------------------------------
__global__ __launch_bounds__(256) void k_edge_place(const int* __restrict__ src,
                                                    const int* __restrict__ dst,
                                                    int n_edges) {
    int e = blockIdx.x * blockDim.x + threadIdx.x;
    if (e >= n_edges) return;
    int s = src[e];
    int d = dst[e];
    float t = __ldg(&g_ssrc[s]) + g_se[e];
    int pos = atomicAdd(&g_cursor[d], 1);
    uint2 v;
    v.x = (unsigned)s;
    v.y = __float_as_uint(t);
    g_pe[pos] = v;
}

// ---------------------------------------------------------------------------
// K5: warp per dst node: w_e = exp(leaky(t_e + sdst[d])) computed vectorized;
//     h[d] = (sum w_e * zh[src_e]) / (sum w_e). Gather loop unrolled x4 (MLP).
// ---------------------------------------------------------------------------
__global__ __launch_bounds__(256) void k_agg(float* __restrict__ out, int n_nodes) {
    int d = (blockIdx.x * blockDim.x + threadIdx.x) >> 5;
    int lane = threadIdx.x & 31;
    if (d >= n_nodes) return;
    int start = g_start[d];
    int deg = g_cursor[d] - start;
    float sdst_d = g_sdst[d];
    float4 acc = make_float4(0.f, 0.f, 0.f, 0.f);
    float wsum = 0.f;

    for (int i = 0; i < deg; i += 32) {
        int s = 0;
        float wv = 0.f;
        if (i + lane < deg) {
            uint2 p = g_pe[start + i + lane];
            s = (int)p.x;
            float ev = __uint_as_float(p.y) + sdst_d;
            ev = (ev > 0.f) ? ev : 0.01f * ev;
            wv = __expf(ev);
        }
        wsum += wv;
        int cnt = min(32, deg - i);
        int j = 0;
        for (; j + 4 <= cnt; j += 4) {
            int s0 = __shfl_sync(0xffffffffu, s, j);
            int s1 = __shfl_sync(0xffffffffu, s, j + 1);
            int s2 = __shfl_sync(0xffffffffu, s, j + 2);
            int s3 = __shfl_sync(0xffffffffu, s, j + 3);
            float w0 = __shfl_sync(0xffffffffu, wv, j);
            float w1 = __shfl_sync(0xffffffffu, wv, j + 1);
            float w2 = __shfl_sync(0xffffffffu, wv, j + 2);
            float w3 = __shfl_sync(0xffffffffu, wv, j + 3);
            uint2 h0 = *reinterpret_cast<const uint2*>(g_zh + (size_t)s0 * 128 + lane * 4);
            uint2 h1 = *reinterpret_cast<const uint2*>(g_zh + (size_t)s1 * 128 + lane * 4);
            uint2 h2 = *reinterpret_cast<const uint2*>(g_zh + (size_t)s2 * 128 + lane * 4);
            uint2 h3 = *reinterpret_cast<const uint2*>(g_zh + (size_t)s3 * 128 + lane * 4);
#define ACC_EDGE(hz, wj)                                                   \
            {                                                              \
                float2 f01 = __half22float2(*reinterpret_cast<__half2*>(&hz.x)); \
                float2 f23 = __half22float2(*reinterpret_cast<__half2*>(&hz.y)); \
                acc.x += (wj) * f01.x;                                     \
                acc.y += (wj) * f01.y;                                     \
                acc.z += (wj) * f23.x;                                     \
                acc.w += (wj) * f23.y;                                     \
            }
            ACC_EDGE(h0, w0)
            ACC_EDGE(h1, w1)
            ACC_EDGE(h2, w2)
            ACC_EDGE(h3, w3)
        }
        for (; j < cnt; j++) {
            int sj = __shfl_sync(0xffffffffu, s, j);
            float wj = __shfl_sync(0xffffffffu, wv, j);
            uint2 hz = *reinterpret_cast<const uint2*>(g_zh + (size_t)sj * 128 + lane * 4);
            ACC_EDGE(hz, wj)
        }
#undef ACC_EDGE
    }
    wsum = warp_sum(wsum);
    float dinv = (wsum > 0.f) ? 1.0f / wsum : 0.f;
    ((float4*)out)[d * 32 + lane] =
        make_float4(acc.x * dinv, acc.y * dinv, acc.z * dinv, acc.w * dinv);
}

// ---------------------------------------------------------------------------
extern "C" void kernel_launch(void* const* d_in, const int* in_sizes, int n_in,
                              void* d_out, int out_size) {
    const float* nf  = (const float*)d_in[0];
    const float* ef  = (const float*)d_in[1];
    const float* Wfc = (const float*)d_in[2];
    const float* Wa  = (const float*)d_in[3];
    const int*   src = (const int*)d_in[4];
    const int*   dst = (const int*)d_in[5];
    float* out = (float*)d_out;

    int n_nodes = in_sizes[0] / 128;
    int n_edges = in_sizes[4];
    int nscan = (n_nodes + 255) / 256;  // 196 (<= 256)

    cudaFuncSetAttribute(k_gemm_h, cudaFuncAttributeMaxDynamicSharedMemorySize, GEMMH_SMEM);

    k_zero<<<(n_nodes + 255) / 256, 256>>>(n_nodes);
    k_gemm_h<<<(n_nodes + 127) / 128, 256, GEMMH_SMEM>>>(nf, Wfc, Wa, n_nodes);
    k_se_hist<<<(n_edges + 255) / 256, 256>>>(ef, Wa, dst, n_edges);
    k_scan1<<<nscan, 256>>>(n_nodes);
    k_scan2<<<1, 256>>>(nscan);
    k_scan3<<<nscan, 256>>>(n_nodes);
    k_edge_place<<<(n_edges + 255) / 256, 256>>>(src, dst, n_edges);
    k_agg<<<(n_nodes + 7) / 8, 256>>>(out, n_nodes);
}